// round 11
// baseline (speedup 1.0000x reference)
#include <cuda_runtime.h>
#include <cuda_bf16.h>

// DCT-II coefficients: A = 1/sqrt(8), Ck = 0.5*cos(k*pi/16)
#define CA 0.35355339059327373f
#define K1 0.4903926402016152f
#define K2 0.46193976625564337f
#define K3 0.4157348061512726f
#define K5 0.27778511650980114f
#define K6 0.19134171618254492f
#define K7 0.09754516100806417f

// invQ[kl] = 100 / LUMINANCE_QUANTIZATION_TABLE[k][l]
__constant__ float INVQ[64] = {
    100.0f/16.0f, 100.0f/11.0f, 100.0f/10.0f, 100.0f/16.0f, 100.0f/24.0f, 100.0f/40.0f,  100.0f/51.0f,  100.0f/61.0f,
    100.0f/12.0f, 100.0f/12.0f, 100.0f/14.0f, 100.0f/19.0f, 100.0f/26.0f, 100.0f/58.0f,  100.0f/60.0f,  100.0f/55.0f,
    100.0f/14.0f, 100.0f/13.0f, 100.0f/16.0f, 100.0f/24.0f, 100.0f/40.0f, 100.0f/57.0f,  100.0f/69.0f,  100.0f/56.0f,
    100.0f/14.0f, 100.0f/17.0f, 100.0f/22.0f, 100.0f/29.0f, 100.0f/51.0f, 100.0f/87.0f,  100.0f/80.0f,  100.0f/62.0f,
    100.0f/18.0f, 100.0f/22.0f, 100.0f/37.0f, 100.0f/56.0f, 100.0f/68.0f, 100.0f/109.0f, 100.0f/103.0f, 100.0f/77.0f,
    100.0f/24.0f, 100.0f/36.0f, 100.0f/55.0f, 100.0f/64.0f, 100.0f/81.0f, 100.0f/104.0f, 100.0f/113.0f, 100.0f/92.0f,
    100.0f/49.0f, 100.0f/64.0f, 100.0f/78.0f, 100.0f/87.0f, 100.0f/103.0f,100.0f/121.0f, 100.0f/120.0f, 100.0f/101.0f,
    100.0f/72.0f, 100.0f/92.0f, 100.0f/95.0f, 100.0f/98.0f, 100.0f/112.0f,100.0f/100.0f, 100.0f/103.0f, 100.0f/99.0f
};

// Sel-free exchange: m_j = shfl_xor(x[3-j]) gives, for both parities, the
// mirror partner of my local col j. Then u_j = x_j + m_j, v_j = x_j - m_j:
//   q=0: u_j = s_j,      v_j =  d_j
//   q=1: u_j = s_{3-j},  v_j = -d_{3-j}
// E0=u0+u3, E1=u1+u2 equal e0,e1 for both parities; F0=u0-u3, F1=u1-u2 equal
// (f0,f1) for q=0 and (-f0,-f1) for q=1. Reversal/sign folded into this table:
//   [0]=cA (ya = CA*E0 + cA*E1), [1,2]=cb (yb = cb0*F0 + cb1*F1),
//   [3..6]=cc (yc = cc.v), [7..10]=cd (yd = cd.v)
// q=0 -> (y0,y1,y2,y3); q=1 -> (y4,y5,y6,y7).
__constant__ float CC[2][11] = {
  { CA,   K2,  K6,   K1,  K3,  K5,  K7,   K3, -K7, -K1, -K5},
  {-CA,  -K6,  K2,  -K3, -K7,  K1, -K5,   K1, -K3,  K5, -K7}
};

// full 8-point orthonormal DCT-II butterfly (column pass, thread-local, in-place)
__device__ __forceinline__ void dct8(float* __restrict__ x) {
    float s0 = x[0] + x[7], s1 = x[1] + x[6], s2 = x[2] + x[5], s3 = x[3] + x[4];
    float d0 = x[0] - x[7], d1 = x[1] - x[6], d2 = x[2] - x[5], d3 = x[3] - x[4];
    float e0 = s0 + s3, e1 = s1 + s2;
    float f0 = s0 - s3, f1 = s1 - s2;
    x[0] = CA * (e0 + e1);
    x[4] = CA * (e0 - e1);
    x[2] = K2 * f0 + K6 * f1;
    x[6] = K6 * f0 - K2 * f1;
    x[1] = K1 * d0 + K3 * d1 + K5 * d2 + K7 * d3;
    x[3] = K3 * d0 - K7 * d1 - K1 * d2 - K5 * d3;
    x[5] = K5 * d0 - K1 * d1 + K7 * d2 + K3 * d3;
    x[7] = K7 * d0 - K5 * d1 + K3 * d2 - K1 * d3;
}

// 2 threads per 8x8 block (column halves). CTA = 256 threads = 128 blocks
// = one full (b, hb) row of blocks. Grid = 16*128 = 2048 CTAs.
// All 8 loads hoisted (MLP=8) — measured faster than in-loop loads despite
// higher regs/lower occupancy (R6 vs R9).
__global__ __launch_bounds__(256, 4) void jpeg_dct_kernel(
    const float* __restrict__ img,   // [16, 1, 1024, 1024]
    const float* __restrict__ qf,    // [16]
    float* __restrict__ out)         // [16, 64, 128, 128]
{
    const int t  = threadIdx.x;
    const int q  = t & 1;            // column half
    const int tb = t >> 1;           // wb 0..127
    const int b  = blockIdx.x >> 7;
    const int hb = blockIdx.x & 127;

    // load my half-rows: q=0 -> cols 0..3, q=1 -> cols 4..7
    const float* p = img + ((size_t)b << 20) + ((size_t)hb << 13) + (tb << 3) + (q << 2);
    float4 X[8];
#pragma unroll
    for (int r = 0; r < 8; r++)
        X[r] = *reinterpret_cast<const float4*>(p + ((size_t)r << 10));

    // per-q coefficients
    const float* cc = CC[q];
    const float cA  = cc[0];
    const float cb0 = cc[1], cb1 = cc[2];
    const float cc0 = cc[3], cc1 = cc[4], cc2 = cc[5], cc3 = cc[6];
    const float cd0 = cc[7], cd1 = cc[8], cd2 = cc[9], cd3 = cc[10];

    // row pass -> T[j][r] = T-matrix column (l = j + 4q)
    float T[4][8];
#pragma unroll
    for (int r = 0; r < 8; r++) {
        // mirror exchange, no selects: m_j = partner's local col (3-j)
        float m0 = __shfl_xor_sync(0xffffffffu, X[r].w, 1);
        float m1 = __shfl_xor_sync(0xffffffffu, X[r].z, 1);
        float m2 = __shfl_xor_sync(0xffffffffu, X[r].y, 1);
        float m3 = __shfl_xor_sync(0xffffffffu, X[r].x, 1);
        float u0 = X[r].x + m0, u1 = X[r].y + m1, u2 = X[r].z + m2, u3 = X[r].w + m3;
        float v0 = X[r].x - m0, v1 = X[r].y - m1, v2 = X[r].z - m2, v3 = X[r].w - m3;
        float E0 = u0 + u3, E1 = u1 + u2;
        float F0 = u0 - u3, F1 = u1 - u2;
        T[0][r] = fmaf(cA, E1, CA * E0);                                    // y0 / y4
        T[1][r] = fmaf(cc3, v3, fmaf(cc2, v2, fmaf(cc1, v1, cc0 * v0)));    // y1 / y5
        T[2][r] = fmaf(cb1, F1, cb0 * F0);                                  // y2 / y6
        T[3][r] = fmaf(cd3, v3, fmaf(cd2, v2, fmaf(cd1, v1, cd0 * v0)));    // y3 / y7
    }

    // column pass: in-place, fully thread-local
#pragma unroll
    for (int j = 0; j < 4; j++) dct8(T[j]);

    // -128 centering affects only the DC term Y[0][0] (owned by q==0, j==0)
    if (q == 0) T[0][0] -= 1024.0f;

    // quantization scale
    float qv = qf[b];
    float invf = (qv < 50.0f) ? (qv * 2.0e-4f) : (1.0f / (200.0f - 2.0f * qv));

    // stores: plane kl = k*8 + j + 4q at (hb, wb=tb); 4q folded into base so
    // all 32 per-store offsets are compile-time immediates.
    float* o = out + ((size_t)b << 20) + ((size_t)(q << 2) << 14) + (hb << 7) + tb;
#pragma unroll
    for (int k = 0; k < 8; k++) {
#pragma unroll
        for (int j = 0; j < 4; j++) {
            int kl = (k << 3) + j + (q << 2);
            o[(size_t)((k << 3) + j) << 14] = T[j][k] * (INVQ[kl] * invf);
        }
    }
}

extern "C" void kernel_launch(void* const* d_in, const int* in_sizes, int n_in,
                              void* d_out, int out_size) {
    const float* img = (const float*)d_in[0];
    const float* qf  = (const float*)d_in[1];
    float* out = (float*)d_out;
    jpeg_dct_kernel<<<2048, 256>>>(img, qf, out);
}

// round 14
// speedup vs baseline: 1.0380x; 1.0380x over previous
#include <cuda_runtime.h>
#include <cuda_bf16.h>

// DCT-II coefficients: A = 1/sqrt(8), Ck = 0.5*cos(k*pi/16)
#define CA 0.35355339059327373f
#define K1 0.4903926402016152f
#define K2 0.46193976625564337f
#define K3 0.4157348061512726f
#define K5 0.27778511650980114f
#define K6 0.19134171618254492f
#define K7 0.09754516100806417f

// invQ[kl] = 100 / LUMINANCE_QUANTIZATION_TABLE[k][l]
__constant__ float INVQ[64] = {
    100.0f/16.0f, 100.0f/11.0f, 100.0f/10.0f, 100.0f/16.0f, 100.0f/24.0f, 100.0f/40.0f,  100.0f/51.0f,  100.0f/61.0f,
    100.0f/12.0f, 100.0f/12.0f, 100.0f/14.0f, 100.0f/19.0f, 100.0f/26.0f, 100.0f/58.0f,  100.0f/60.0f,  100.0f/55.0f,
    100.0f/14.0f, 100.0f/13.0f, 100.0f/16.0f, 100.0f/24.0f, 100.0f/40.0f, 100.0f/57.0f,  100.0f/69.0f,  100.0f/56.0f,
    100.0f/14.0f, 100.0f/17.0f, 100.0f/22.0f, 100.0f/29.0f, 100.0f/51.0f, 100.0f/87.0f,  100.0f/80.0f,  100.0f/62.0f,
    100.0f/18.0f, 100.0f/22.0f, 100.0f/37.0f, 100.0f/56.0f, 100.0f/68.0f, 100.0f/109.0f, 100.0f/103.0f, 100.0f/77.0f,
    100.0f/24.0f, 100.0f/36.0f, 100.0f/55.0f, 100.0f/64.0f, 100.0f/81.0f, 100.0f/104.0f, 100.0f/113.0f, 100.0f/92.0f,
    100.0f/49.0f, 100.0f/64.0f, 100.0f/78.0f, 100.0f/87.0f, 100.0f/103.0f,100.0f/121.0f, 100.0f/120.0f, 100.0f/101.0f,
    100.0f/72.0f, 100.0f/92.0f, 100.0f/95.0f, 100.0f/98.0f, 100.0f/112.0f,100.0f/100.0f, 100.0f/103.0f, 100.0f/99.0f
};

// Sel-free exchange: m_j = shfl_xor(x[3-j]) gives, for both parities, the
// mirror partner of my local col j. Then u_j = x_j + m_j, v_j = x_j - m_j:
//   q=0: u_j = s_j,      v_j =  d_j
//   q=1: u_j = s_{3-j},  v_j = -d_{3-j}
// Reversal/sign folded into this table (see R9/R11 derivation).
// q=0 -> (y0,y1,y2,y3); q=1 -> (y4,y5,y6,y7).
__constant__ float CC[2][11] = {
  { CA,   K2,  K6,   K1,  K3,  K5,  K7,   K3, -K7, -K1, -K5},
  {-CA,  -K6,  K2,  -K3, -K7,  K1, -K5,   K1, -K3,  K5, -K7}
};

// full 8-point orthonormal DCT-II butterfly (column pass, thread-local, in-place)
__device__ __forceinline__ void dct8(float* __restrict__ x) {
    float s0 = x[0] + x[7], s1 = x[1] + x[6], s2 = x[2] + x[5], s3 = x[3] + x[4];
    float d0 = x[0] - x[7], d1 = x[1] - x[6], d2 = x[2] - x[5], d3 = x[3] - x[4];
    float e0 = s0 + s3, e1 = s1 + s2;
    float f0 = s0 - s3, f1 = s1 - s2;
    x[0] = CA * (e0 + e1);
    x[4] = CA * (e0 - e1);
    x[2] = K2 * f0 + K6 * f1;
    x[6] = K6 * f0 - K2 * f1;
    x[1] = K1 * d0 + K3 * d1 + K5 * d2 + K7 * d3;
    x[3] = K3 * d0 - K7 * d1 - K1 * d2 - K5 * d3;
    x[5] = K5 * d0 - K1 * d1 + K7 * d2 + K3 * d3;
    x[7] = K7 * d0 - K5 * d1 + K3 * d2 - K1 * d3;
}

// 2 threads per 8x8 block (column halves). CTA = 256 threads = 128 blocks
// = one full (b, hb) row of blocks. Grid = 16*128 = 2048 CTAs.
// Output stores are streaming (__stcs, evict-first): output is never re-read,
// and keeping it out of L2 preserves input residency across graph replays.
__global__ __launch_bounds__(256, 4) void jpeg_dct_kernel(
    const float* __restrict__ img,   // [16, 1, 1024, 1024]
    const float* __restrict__ qf,    // [16]
    float* __restrict__ out)         // [16, 64, 128, 128]
{
    const int t  = threadIdx.x;
    const int q  = t & 1;            // column half
    const int tb = t >> 1;           // wb 0..127
    const int b  = blockIdx.x >> 7;
    const int hb = blockIdx.x & 127;

    // load my half-rows: q=0 -> cols 0..3, q=1 -> cols 4..7
    const float* p = img + ((size_t)b << 20) + ((size_t)hb << 13) + (tb << 3) + (q << 2);
    float4 X[8];
#pragma unroll
    for (int r = 0; r < 8; r++)
        X[r] = *reinterpret_cast<const float4*>(p + ((size_t)r << 10));

    // per-q coefficients
    const float* cc = CC[q];
    const float cA  = cc[0];
    const float cb0 = cc[1], cb1 = cc[2];
    const float cc0 = cc[3], cc1 = cc[4], cc2 = cc[5], cc3 = cc[6];
    const float cd0 = cc[7], cd1 = cc[8], cd2 = cc[9], cd3 = cc[10];

    // row pass -> T[j][r] = T-matrix column (l = j + 4q)
    float T[4][8];
#pragma unroll
    for (int r = 0; r < 8; r++) {
        // mirror exchange, no selects: m_j = partner's local col (3-j)
        float m0 = __shfl_xor_sync(0xffffffffu, X[r].w, 1);
        float m1 = __shfl_xor_sync(0xffffffffu, X[r].z, 1);
        float m2 = __shfl_xor_sync(0xffffffffu, X[r].y, 1);
        float m3 = __shfl_xor_sync(0xffffffffu, X[r].x, 1);
        float u0 = X[r].x + m0, u1 = X[r].y + m1, u2 = X[r].z + m2, u3 = X[r].w + m3;
        float v0 = X[r].x - m0, v1 = X[r].y - m1, v2 = X[r].z - m2, v3 = X[r].w - m3;
        float E0 = u0 + u3, E1 = u1 + u2;
        float F0 = u0 - u3, F1 = u1 - u2;
        T[0][r] = fmaf(cA, E1, CA * E0);                                    // y0 / y4
        T[1][r] = fmaf(cc3, v3, fmaf(cc2, v2, fmaf(cc1, v1, cc0 * v0)));    // y1 / y5
        T[2][r] = fmaf(cb1, F1, cb0 * F0);                                  // y2 / y6
        T[3][r] = fmaf(cd3, v3, fmaf(cd2, v2, fmaf(cd1, v1, cd0 * v0)));    // y3 / y7
    }

    // column pass: in-place, fully thread-local
#pragma unroll
    for (int j = 0; j < 4; j++) dct8(T[j]);

    // -128 centering affects only the DC term Y[0][0] (owned by q==0, j==0)
    if (q == 0) T[0][0] -= 1024.0f;

    // quantization scale
    float qv = qf[b];
    float invf = (qv < 50.0f) ? (qv * 2.0e-4f) : (1.0f / (200.0f - 2.0f * qv));

    // stores: plane kl = k*8 + j + 4q at (hb, wb=tb); streaming (.cs) so the
    // write stream evicts first and doesn't thrash input L2 residency.
    float* o = out + ((size_t)b << 20) + ((size_t)(q << 2) << 14) + (hb << 7) + tb;
#pragma unroll
    for (int k = 0; k < 8; k++) {
#pragma unroll
        for (int j = 0; j < 4; j++) {
            int kl = (k << 3) + j + (q << 2);
            __stcs(&o[(size_t)((k << 3) + j) << 14], T[j][k] * (INVQ[kl] * invf));
        }
    }
}

extern "C" void kernel_launch(void* const* d_in, const int* in_sizes, int n_in,
                              void* d_out, int out_size) {
    const float* img = (const float*)d_in[0];
    const float* qf  = (const float*)d_in[1];
    float* out = (float*)d_out;
    jpeg_dct_kernel<<<2048, 256>>>(img, qf, out);
}